// round 1
// baseline (speedup 1.0000x reference)
#include <cuda_runtime.h>

#define NNODES 50000
#define FDIM   128
#define DEG    16

// Scratch (no allocations allowed -> __device__ globals)
__device__ float g_A[NNODES * FDIM];        // x @ Wm_top
__device__ float g_B[NNODES * FDIM];        // x @ Wm_bot
__device__ float g_xnew[NNODES * FDIM];     // x + agg
__device__ float g_support[NNODES * FDIM];  // x_new @ weight

// ---------------------------------------------------------------------------
// C[M,128] = X[M,128] @ W[128,128]   (fp32 SIMT tiled GEMM, BM=128, BK=16)
// 256 threads, each computes an 8x8 microtile.
// ---------------------------------------------------------------------------
__global__ __launch_bounds__(256, 1) void gemm_kernel(
    const float* __restrict__ X, const float* __restrict__ W,
    float* __restrict__ C, int M)
{
    __shared__ float Xs[16][128 + 4];   // k-major, padded
    __shared__ float Ws[16][128];

    const int tid  = threadIdx.x;
    const int tx   = tid & 15;   // N-dim group (8 cols each)
    const int ty   = tid >> 4;   // M-dim group (8 rows each)
    const int row0 = blockIdx.x * 128;

    float acc[8][8];
#pragma unroll
    for (int i = 0; i < 8; ++i)
#pragma unroll
        for (int j = 0; j < 8; ++j) acc[i][j] = 0.f;

    for (int k0 = 0; k0 < 128; k0 += 16) {
        // load X tile (128 rows x 16 k) transposed into Xs[k][row]
#pragma unroll
        for (int it = 0; it < 8; ++it) {
            int idx  = tid + it * 256;
            int r    = idx >> 4;
            int c    = idx & 15;
            int grow = row0 + r;
            Xs[c][r] = (grow < M) ? X[grow * 128 + k0 + c] : 0.f;
        }
        // load W tile (16 k x 128 n)
#pragma unroll
        for (int it = 0; it < 8; ++it) {
            int idx = tid + it * 256;
            int r   = idx >> 7;
            int c   = idx & 127;
            Ws[r][c] = W[(k0 + r) * 128 + c];
        }
        __syncthreads();
#pragma unroll
        for (int kk = 0; kk < 16; ++kk) {
            float a[8], b[8];
#pragma unroll
            for (int i = 0; i < 8; ++i) a[i] = Xs[kk][ty * 8 + i];
#pragma unroll
            for (int j = 0; j < 8; ++j) b[j] = Ws[kk][tx * 8 + j];
#pragma unroll
            for (int i = 0; i < 8; ++i)
#pragma unroll
                for (int j = 0; j < 8; ++j)
                    acc[i][j] = fmaf(a[i], b[j], acc[i][j]);
        }
        __syncthreads();
    }

#pragma unroll
    for (int i = 0; i < 8; ++i) {
        int grow = row0 + ty * 8 + i;
        if (grow < M) {
            float4* p = reinterpret_cast<float4*>(C + (size_t)grow * 128 + tx * 8);
            p[0] = make_float4(acc[i][0], acc[i][1], acc[i][2], acc[i][3]);
            p[1] = make_float4(acc[i][4], acc[i][5], acc[i][6], acc[i][7]);
        }
    }
}

__device__ __forceinline__ float sigmoidf_(float v) {
    return 1.0f / (1.0f + __expf(-v));
}

// ---------------------------------------------------------------------------
// Per-node (16 consecutive edges share dst):
//   agg[dst] = sum_d sigmoid(A[dst] + B[src_d]) * x[src_d]
//   x_new[dst] = x[dst] + agg[dst]
// One warp per node; each lane owns a float4 (4 features).
// ---------------------------------------------------------------------------
__global__ __launch_bounds__(128) void mask_agg_kernel(
    const float* __restrict__ x, const int* __restrict__ esrc,
    const int* __restrict__ edst)
{
    const int warp = threadIdx.x >> 5;
    const int lane = threadIdx.x & 31;
    const int node = blockIdx.x * 4 + warp;
    if (node >= NNODES) return;

    const int ebase = node * DEG;
    const int dst   = edst[ebase];   // all 16 edges of this group share dst

    const float4 a = *reinterpret_cast<const float4*>(g_A + (size_t)dst * FDIM + lane * 4);
    float4 acc = make_float4(0.f, 0.f, 0.f, 0.f);

    int srcs[DEG];
#pragma unroll
    for (int d = 0; d < DEG; ++d) srcs[d] = esrc[ebase + d];

#pragma unroll
    for (int d = 0; d < DEG; ++d) {
        const float4 b  = *reinterpret_cast<const float4*>(g_B + (size_t)srcs[d] * FDIM + lane * 4);
        const float4 nv = *reinterpret_cast<const float4*>(x   + (size_t)srcs[d] * FDIM + lane * 4);
        acc.x = fmaf(sigmoidf_(a.x + b.x), nv.x, acc.x);
        acc.y = fmaf(sigmoidf_(a.y + b.y), nv.y, acc.y);
        acc.z = fmaf(sigmoidf_(a.z + b.z), nv.z, acc.z);
        acc.w = fmaf(sigmoidf_(a.w + b.w), nv.w, acc.w);
    }

    const float4 xv = *reinterpret_cast<const float4*>(x + (size_t)dst * FDIM + lane * 4);
    acc.x += xv.x; acc.y += xv.y; acc.z += xv.z; acc.w += xv.w;
    *reinterpret_cast<float4*>(g_xnew + (size_t)dst * FDIM + lane * 4) = acc;
}

// ---------------------------------------------------------------------------
// out[dst] = bias + sum_d adj[e] * support[src_d]
// ---------------------------------------------------------------------------
__global__ __launch_bounds__(128) void spmm_kernel(
    const float* __restrict__ adj, const int* __restrict__ esrc,
    const int* __restrict__ edst, const float* __restrict__ bias,
    float* __restrict__ out)
{
    const int warp = threadIdx.x >> 5;
    const int lane = threadIdx.x & 31;
    const int node = blockIdx.x * 4 + warp;
    if (node >= NNODES) return;

    const int ebase = node * DEG;
    const int dst   = edst[ebase];

    float4 acc = *reinterpret_cast<const float4*>(bias + lane * 4);

    int   srcs[DEG];
    float av[DEG];
#pragma unroll
    for (int d = 0; d < DEG; ++d) { srcs[d] = esrc[ebase + d]; av[d] = adj[ebase + d]; }

#pragma unroll
    for (int d = 0; d < DEG; ++d) {
        const float4 sv = *reinterpret_cast<const float4*>(g_support + (size_t)srcs[d] * FDIM + lane * 4);
        acc.x = fmaf(av[d], sv.x, acc.x);
        acc.y = fmaf(av[d], sv.y, acc.y);
        acc.z = fmaf(av[d], sv.z, acc.z);
        acc.w = fmaf(av[d], sv.w, acc.w);
    }
    *reinterpret_cast<float4*>(out + (size_t)dst * FDIM + lane * 4) = acc;
}

// ---------------------------------------------------------------------------
extern "C" void kernel_launch(void* const* d_in, const int* in_sizes, int n_in,
                              void* d_out, int out_size)
{
    const float* x      = (const float*)d_in[0];
    const float* weight = (const float*)d_in[1];
    const float* bias   = (const float*)d_in[2];
    const float* wmask  = (const float*)d_in[3];
    const float* adj    = (const float*)d_in[4];
    const int*   esrc   = (const int*)d_in[5];
    const int*   edst   = (const int*)d_in[6];
    float*       out    = (float*)d_out;

    float *pA, *pB, *pXn, *pS;
    cudaGetSymbolAddress((void**)&pA,  g_A);
    cudaGetSymbolAddress((void**)&pB,  g_B);
    cudaGetSymbolAddress((void**)&pXn, g_xnew);
    cudaGetSymbolAddress((void**)&pS,  g_support);

    const int gemm_blocks = (NNODES + 127) / 128;
    const int node_blocks = (NNODES + 3) / 4;

    // A = x @ Wm[0:128,:]   B = x @ Wm[128:256,:]
    gemm_kernel<<<gemm_blocks, 256>>>(x, wmask,                pA, NNODES);
    gemm_kernel<<<gemm_blocks, 256>>>(x, wmask + 128 * 128,    pB, NNODES);
    // mask + neighbor aggregation -> x_new
    mask_agg_kernel<<<node_blocks, 128>>>(x, esrc, edst);
    // support = x_new @ weight
    gemm_kernel<<<gemm_blocks, 256>>>(pXn, weight, pS, NNODES);
    // out = segment_sum(adj * support[src]) + bias
    spmm_kernel<<<node_blocks, 128>>>(adj, esrc, edst, bias, out);
}

// round 3
// speedup vs baseline: 1.6100x; 1.6100x over previous
#include <cuda_runtime.h>
#include <cstdint>

#define NNODES 50000
#define FDIM   128
#define DEG    16

// Scratch (no allocations allowed -> __device__ globals)
__device__ float g_A[NNODES * FDIM];        // x @ Wm_top
__device__ float g_B[NNODES * FDIM];        // x @ Wm_bot
__device__ float g_xnew[NNODES * FDIM];     // x + agg
__device__ float g_support[NNODES * FDIM];  // x_new @ weight

__device__ __forceinline__ float tf32r(float v) {
    uint32_t o;
    asm("cvt.rna.tf32.f32 %0, %1;" : "=r"(o) : "f"(v));
    return __uint_as_float(o);
}

__device__ __forceinline__ void mma_tf32(
    float& c0, float& c1, float& c2, float& c3,
    uint32_t a0, uint32_t a1, uint32_t a2, uint32_t a3,
    uint32_t b0, uint32_t b1)
{
    asm volatile(
        "mma.sync.aligned.m16n8k8.row.col.f32.tf32.tf32.f32 "
        "{%0,%1,%2,%3}, {%4,%5,%6,%7}, {%8,%9}, {%0,%1,%2,%3};"
        : "+f"(c0), "+f"(c1), "+f"(c2), "+f"(c3)
        : "r"(a0), "r"(a1), "r"(a2), "r"(a3), "r"(b0), "r"(b1));
}

// ===========================================================================
// C[M,128] = X[M,128] @ W[128,128]  (tf32 mma.sync, BM=128, BN=128, BK=32)
// 8 warps in 4x2; warp tile 32x64 = 2 m16-tiles x 8 n8-tiles.
// Xs rows padded to 36 floats, Ws rows padded to 136 floats (both give
// conflict-free fragment gathers: bank = 4r+k resp. 8k+n, bijective/warp).
// ===========================================================================
__global__ __launch_bounds__(256, 2) void gemm_mma(
    const float* __restrict__ X, const float* __restrict__ W,
    float* __restrict__ C, int M)
{
    __shared__ float Xs[128][36];
    __shared__ float Ws[32][136];

    const int tid  = threadIdx.x;
    const int lane = tid & 31;
    const int wid  = tid >> 5;
    const int wm   = wid & 3;        // 32-row band
    const int wn   = wid >> 2;       // 64-col band
    const int row0 = blockIdx.x * 128;
    const int lq   = lane >> 2;      // lane / 4
    const int lr   = lane & 3;       // lane % 4

    float c[2][8][4];
#pragma unroll
    for (int mt = 0; mt < 2; ++mt)
#pragma unroll
        for (int nt = 0; nt < 8; ++nt)
#pragma unroll
            for (int j = 0; j < 4; ++j) c[mt][nt][j] = 0.f;

    for (int k0 = 0; k0 < 128; k0 += 32) {
        // X slab: 128 rows x 32 k   (1024 float4, 4 per thread)
#pragma unroll
        for (int it = 0; it < 4; ++it) {
            int idx = tid + it * 256;
            int r = idx >> 3, c4 = idx & 7;
            float4 v = make_float4(0.f, 0.f, 0.f, 0.f);
            if (row0 + r < M)
                v = *reinterpret_cast<const float4*>(X + (size_t)(row0 + r) * 128 + k0 + c4 * 4);
            v.x = tf32r(v.x); v.y = tf32r(v.y); v.z = tf32r(v.z); v.w = tf32r(v.w);
            *reinterpret_cast<float4*>(&Xs[r][c4 * 4]) = v;
        }
        // W slab: 32 k x 128 n
#pragma unroll
        for (int it = 0; it < 4; ++it) {
            int idx = tid + it * 256;
            int kr = idx >> 5, c4 = idx & 31;
            float4 v = *reinterpret_cast<const float4*>(W + (size_t)(k0 + kr) * 128 + c4 * 4);
            v.x = tf32r(v.x); v.y = tf32r(v.y); v.z = tf32r(v.z); v.w = tf32r(v.w);
            *reinterpret_cast<float4*>(&Ws[kr][c4 * 4]) = v;
        }
        __syncthreads();

#pragma unroll
        for (int kk = 0; kk < 4; ++kk) {
            const int kb = kk * 8;
            uint32_t a[2][4], b[8][2];
#pragma unroll
            for (int mt = 0; mt < 2; ++mt) {
                int rb = wm * 32 + mt * 16 + lq;
                a[mt][0] = __float_as_uint(Xs[rb    ][kb     + lr]);
                a[mt][1] = __float_as_uint(Xs[rb + 8][kb     + lr]);
                a[mt][2] = __float_as_uint(Xs[rb    ][kb + 4 + lr]);
                a[mt][3] = __float_as_uint(Xs[rb + 8][kb + 4 + lr]);
            }
#pragma unroll
            for (int nt = 0; nt < 8; ++nt) {
                int col = wn * 64 + nt * 8 + lq;
                b[nt][0] = __float_as_uint(Ws[kb     + lr][col]);
                b[nt][1] = __float_as_uint(Ws[kb + 4 + lr][col]);
            }
#pragma unroll
            for (int mt = 0; mt < 2; ++mt)
#pragma unroll
                for (int nt = 0; nt < 8; ++nt)
                    mma_tf32(c[mt][nt][0], c[mt][nt][1], c[mt][nt][2], c[mt][nt][3],
                             a[mt][0], a[mt][1], a[mt][2], a[mt][3],
                             b[nt][0], b[nt][1]);
        }
        __syncthreads();
    }

    // Epilogue: c0,c1 at (row, 2*lr), c2,c3 at (row+8, 2*lr)
#pragma unroll
    for (int mt = 0; mt < 2; ++mt) {
        const int r0 = row0 + wm * 32 + mt * 16 + lq;
#pragma unroll
        for (int nt = 0; nt < 8; ++nt) {
            const int col = wn * 64 + nt * 8 + 2 * lr;
            if (r0 < M)
                *reinterpret_cast<float2*>(C + (size_t)r0 * 128 + col) =
                    make_float2(c[mt][nt][0], c[mt][nt][1]);
            if (r0 + 8 < M)
                *reinterpret_cast<float2*>(C + (size_t)(r0 + 8) * 128 + col) =
                    make_float2(c[mt][nt][2], c[mt][nt][3]);
        }
    }
}

// ===========================================================================
// Edge kernels (L2-gather-bound)
// ===========================================================================
__device__ __forceinline__ float sigmoidf_(float v) {
    return 1.0f / (1.0f + __expf(-v));
}

__global__ __launch_bounds__(128) void mask_agg_kernel(
    const float* __restrict__ x, const int* __restrict__ esrc,
    const int* __restrict__ edst)
{
    const int warp = threadIdx.x >> 5;
    const int lane = threadIdx.x & 31;
    const int node = blockIdx.x * 4 + warp;
    if (node >= NNODES) return;

    const int ebase = node * DEG;
    const int dst   = edst[ebase];

    const float4 a = *reinterpret_cast<const float4*>(g_A + (size_t)dst * FDIM + lane * 4);
    float4 acc = make_float4(0.f, 0.f, 0.f, 0.f);

    int srcs[DEG];
#pragma unroll
    for (int d = 0; d < DEG; ++d) srcs[d] = esrc[ebase + d];

#pragma unroll
    for (int d = 0; d < DEG; ++d) {
        const float4 b  = *reinterpret_cast<const float4*>(g_B + (size_t)srcs[d] * FDIM + lane * 4);
        const float4 nv = *reinterpret_cast<const float4*>(x   + (size_t)srcs[d] * FDIM + lane * 4);
        acc.x = fmaf(sigmoidf_(a.x + b.x), nv.x, acc.x);
        acc.y = fmaf(sigmoidf_(a.y + b.y), nv.y, acc.y);
        acc.z = fmaf(sigmoidf_(a.z + b.z), nv.z, acc.z);
        acc.w = fmaf(sigmoidf_(a.w + b.w), nv.w, acc.w);
    }

    const float4 xv = *reinterpret_cast<const float4*>(x + (size_t)dst * FDIM + lane * 4);
    acc.x += xv.x; acc.y += xv.y; acc.z += xv.z; acc.w += xv.w;
    *reinterpret_cast<float4*>(g_xnew + (size_t)dst * FDIM + lane * 4) = acc;
}

__global__ __launch_bounds__(128) void spmm_kernel(
    const float* __restrict__ adj, const int* __restrict__ esrc,
    const int* __restrict__ edst, const float* __restrict__ bias,
    float* __restrict__ out)
{
    const int warp = threadIdx.x >> 5;
    const int lane = threadIdx.x & 31;
    const int node = blockIdx.x * 4 + warp;
    if (node >= NNODES) return;

    const int ebase = node * DEG;
    const int dst   = edst[ebase];

    float4 acc = *reinterpret_cast<const float4*>(bias + lane * 4);

    int   srcs[DEG];
    float av[DEG];
#pragma unroll
    for (int d = 0; d < DEG; ++d) { srcs[d] = esrc[ebase + d]; av[d] = adj[ebase + d]; }

#pragma unroll
    for (int d = 0; d < DEG; ++d) {
        const float4 sv = *reinterpret_cast<const float4*>(g_support + (size_t)srcs[d] * FDIM + lane * 4);
        acc.x = fmaf(av[d], sv.x, acc.x);
        acc.y = fmaf(av[d], sv.y, acc.y);
        acc.z = fmaf(av[d], sv.z, acc.z);
        acc.w = fmaf(av[d], sv.w, acc.w);
    }
    *reinterpret_cast<float4*>(out + (size_t)dst * FDIM + lane * 4) = acc;
}

// ===========================================================================
extern "C" void kernel_launch(void* const* d_in, const int* in_sizes, int n_in,
                              void* d_out, int out_size)
{
    const float* x      = (const float*)d_in[0];
    const float* weight = (const float*)d_in[1];
    const float* bias   = (const float*)d_in[2];
    const float* wmask  = (const float*)d_in[3];
    const float* adj    = (const float*)d_in[4];
    const int*   esrc   = (const int*)d_in[5];
    const int*   edst   = (const int*)d_in[6];
    float*       out    = (float*)d_out;

    float *pA, *pB, *pXn, *pS;
    cudaGetSymbolAddress((void**)&pA,  g_A);
    cudaGetSymbolAddress((void**)&pB,  g_B);
    cudaGetSymbolAddress((void**)&pXn, g_xnew);
    cudaGetSymbolAddress((void**)&pS,  g_support);

    const int gemm_blocks = (NNODES + 127) / 128;
    const int node_blocks = (NNODES + 3) / 4;

    // A = x @ Wm_top,  B = x @ Wm_bot
    gemm_mma<<<gemm_blocks, 256>>>(x, wmask,             pA, NNODES);
    gemm_mma<<<gemm_blocks, 256>>>(x, wmask + 128 * 128, pB, NNODES);
    // mask + neighbor aggregation -> x_new
    mask_agg_kernel<<<node_blocks, 128>>>(x, esrc, edst);
    // support = x_new @ weight
    gemm_mma<<<gemm_blocks, 256>>>(pXn, weight, pS, NNODES);
    // out = segment_sum(adj * support[src]) + bias
    spmm_kernel<<<node_blocks, 128>>>(adj, esrc, edst, bias, out);
}

// round 4
// speedup vs baseline: 1.6689x; 1.0366x over previous
#include <cuda_runtime.h>
#include <cuda_fp16.h>
#include <cstdint>

#define NNODES 50000
#define FDIM   128
#define DEG    16

// Scratch (no allocations allowed -> __device__ globals)
__device__ float   g_A[NNODES * FDIM];         // x @ Wm_top  (fp32, dst-side coalesced reads)
__device__ __half2 g_BX[NNODES * FDIM];        // per feature: (B_f, x_f) fp16 pair
__device__ __half  g_xnew16[NNODES * FDIM];    // fp16(x + agg)
__device__ float   g_agg2[NNODES * FDIM];      // segment_sum(adj * x_new[src])

__device__ __forceinline__ float tf32r(float v) {
    uint32_t o;
    asm("cvt.rna.tf32.f32 %0, %1;" : "=r"(o) : "f"(v));
    return __uint_as_float(o);
}

__device__ __forceinline__ void mma_tf32(
    float& c0, float& c1, float& c2, float& c3,
    uint32_t a0, uint32_t a1, uint32_t a2, uint32_t a3,
    uint32_t b0, uint32_t b1)
{
    asm volatile(
        "mma.sync.aligned.m16n8k8.row.col.f32.tf32.tf32.f32 "
        "{%0,%1,%2,%3}, {%4,%5,%6,%7}, {%8,%9}, {%0,%1,%2,%3};"
        : "+f"(c0), "+f"(c1), "+f"(c2), "+f"(c3)
        : "r"(a0), "r"(a1), "r"(a2), "r"(a3), "r"(b0), "r"(b1));
}

// ===========================================================================
// C[M,128] = X[M,128] @ W[128,128]  (tf32 mma.sync, BM=128, BN=128, BK=64)
// 8 warps 4x2, warp tile 32x64. Dynamic smem: Xs[128][68] + Ws[64][136]
// (row pads 68 / 136 are both ==4 mod 32 resp ==8 mod 32 -> conflict-free
// fragment gathers: bank = 4r+k resp 8k+n, bijective per warp).
// MODE 0: plain fp32 store (A)
// MODE 1: store interleaved half2(C_f, x_f) into g_BX (B GEMM)
// MODE 2: add bias, store fp32 (final output GEMM)
// ===========================================================================
template <int MODE>
__global__ __launch_bounds__(256, 2) void gemm_mma(
    const float* __restrict__ X, const float* __restrict__ W,
    float* __restrict__ C, const float* __restrict__ aux, int M)
{
    extern __shared__ float dyn[];
    float (*Xs)[68]  = reinterpret_cast<float(*)[68]>(dyn);
    float (*Ws)[136] = reinterpret_cast<float(*)[136]>(dyn + 128 * 68);

    const int tid  = threadIdx.x;
    const int lane = tid & 31;
    const int wid  = tid >> 5;
    const int wm   = wid & 3;
    const int wn   = wid >> 2;
    const int row0 = blockIdx.x * 128;
    const int lq   = lane >> 2;
    const int lr   = lane & 3;

    float c[2][8][4];
#pragma unroll
    for (int mt = 0; mt < 2; ++mt)
#pragma unroll
        for (int nt = 0; nt < 8; ++nt)
#pragma unroll
            for (int j = 0; j < 4; ++j) c[mt][nt][j] = 0.f;

    for (int k0 = 0; k0 < 128; k0 += 64) {
        // X slab: 128 rows x 64 k  (2048 float4)
#pragma unroll
        for (int it = 0; it < 8; ++it) {
            int idx = tid + it * 256;
            int r = idx >> 4, c4 = idx & 15;
            float4 v = make_float4(0.f, 0.f, 0.f, 0.f);
            if (row0 + r < M)
                v = *reinterpret_cast<const float4*>(X + (size_t)(row0 + r) * 128 + k0 + c4 * 4);
            v.x = tf32r(v.x); v.y = tf32r(v.y); v.z = tf32r(v.z); v.w = tf32r(v.w);
            *reinterpret_cast<float4*>(&Xs[r][c4 * 4]) = v;
        }
        // W slab: 64 k x 128 n  (2048 float4)
#pragma unroll
        for (int it = 0; it < 8; ++it) {
            int idx = tid + it * 256;
            int kr = idx >> 5, c4 = idx & 31;
            float4 v = *reinterpret_cast<const float4*>(W + (size_t)(k0 + kr) * 128 + c4 * 4);
            v.x = tf32r(v.x); v.y = tf32r(v.y); v.z = tf32r(v.z); v.w = tf32r(v.w);
            *reinterpret_cast<float4*>(&Ws[kr][c4 * 4]) = v;
        }
        __syncthreads();

#pragma unroll
        for (int kk = 0; kk < 8; ++kk) {
            const int kb = kk * 8;
            uint32_t a[2][4], b[8][2];
#pragma unroll
            for (int mt = 0; mt < 2; ++mt) {
                int rb = wm * 32 + mt * 16 + lq;
                a[mt][0] = __float_as_uint(Xs[rb    ][kb     + lr]);
                a[mt][1] = __float_as_uint(Xs[rb + 8][kb     + lr]);
                a[mt][2] = __float_as_uint(Xs[rb    ][kb + 4 + lr]);
                a[mt][3] = __float_as_uint(Xs[rb + 8][kb + 4 + lr]);
            }
#pragma unroll
            for (int nt = 0; nt < 8; ++nt) {
                int col = wn * 64 + nt * 8 + lq;
                b[nt][0] = __float_as_uint(Ws[kb     + lr][col]);
                b[nt][1] = __float_as_uint(Ws[kb + 4 + lr][col]);
            }
#pragma unroll
            for (int mt = 0; mt < 2; ++mt)
#pragma unroll
                for (int nt = 0; nt < 8; ++nt)
                    mma_tf32(c[mt][nt][0], c[mt][nt][1], c[mt][nt][2], c[mt][nt][3],
                             a[mt][0], a[mt][1], a[mt][2], a[mt][3],
                             b[nt][0], b[nt][1]);
        }
        __syncthreads();
    }

    // Epilogue. Fragment layout: c0,c1 -> (row, col..col+1), c2,c3 -> (row+8, ...)
#pragma unroll
    for (int mt = 0; mt < 2; ++mt) {
        const int r0 = row0 + wm * 32 + mt * 16 + lq;
#pragma unroll
        for (int nt = 0; nt < 8; ++nt) {
            const int col = wn * 64 + nt * 8 + 2 * lr;
            if (MODE == 0) {
                if (r0 < M)
                    *reinterpret_cast<float2*>(C + (size_t)r0 * 128 + col) =
                        make_float2(c[mt][nt][0], c[mt][nt][1]);
                if (r0 + 8 < M)
                    *reinterpret_cast<float2*>(C + (size_t)(r0 + 8) * 128 + col) =
                        make_float2(c[mt][nt][2], c[mt][nt][3]);
            } else if (MODE == 1) {
                __half2* BX = reinterpret_cast<__half2*>(C);
                if (r0 < M) {
                    float2 xv = *reinterpret_cast<const float2*>(aux + (size_t)r0 * 128 + col);
                    __half2 p0 = __floats2half2_rn(c[mt][nt][0], xv.x);
                    __half2 p1 = __floats2half2_rn(c[mt][nt][1], xv.y);
                    uint2 pk = make_uint2(*reinterpret_cast<uint32_t*>(&p0),
                                          *reinterpret_cast<uint32_t*>(&p1));
                    *reinterpret_cast<uint2*>(BX + (size_t)r0 * 128 + col) = pk;
                }
                if (r0 + 8 < M) {
                    float2 xv = *reinterpret_cast<const float2*>(aux + (size_t)(r0 + 8) * 128 + col);
                    __half2 p0 = __floats2half2_rn(c[mt][nt][2], xv.x);
                    __half2 p1 = __floats2half2_rn(c[mt][nt][3], xv.y);
                    uint2 pk = make_uint2(*reinterpret_cast<uint32_t*>(&p0),
                                          *reinterpret_cast<uint32_t*>(&p1));
                    *reinterpret_cast<uint2*>(BX + (size_t)(r0 + 8) * 128 + col) = pk;
                }
            } else {
                float2 bv = *reinterpret_cast<const float2*>(aux + col);
                if (r0 < M)
                    *reinterpret_cast<float2*>(C + (size_t)r0 * 128 + col) =
                        make_float2(c[mt][nt][0] + bv.x, c[mt][nt][1] + bv.y);
                if (r0 + 8 < M)
                    *reinterpret_cast<float2*>(C + (size_t)(r0 + 8) * 128 + col) =
                        make_float2(c[mt][nt][2] + bv.x, c[mt][nt][3] + bv.y);
            }
        }
    }
}

// ===========================================================================
// Edge kernels (LTS-gather-bound; fp16-compressed tables)
// ===========================================================================
__device__ __forceinline__ float sigmoidf_(float v) {
    return 1.0f / (1.0f + __expf(-v));
}

// x_new16[dst] = fp16( x[dst] + sum_d sigmoid(A[dst] + B[src]) * x[src] )
__global__ __launch_bounds__(128) void mask_agg_kernel(
    const float* __restrict__ x, const int* __restrict__ esrc,
    const int* __restrict__ edst)
{
    const int warp = threadIdx.x >> 5;
    const int lane = threadIdx.x & 31;
    const int node = blockIdx.x * 4 + warp;
    if (node >= NNODES) return;

    const int ebase = node * DEG;
    const int dst   = edst[ebase];

    const float4 a = *reinterpret_cast<const float4*>(g_A + (size_t)dst * FDIM + lane * 4);
    float4 acc = make_float4(0.f, 0.f, 0.f, 0.f);

    int srcs[DEG];
#pragma unroll
    for (int d = 0; d < DEG; ++d) srcs[d] = esrc[ebase + d];

#pragma unroll
    for (int d = 0; d < DEG; ++d) {
        uint4 raw = *reinterpret_cast<const uint4*>(g_BX + (size_t)srcs[d] * FDIM + lane * 4);
        __half2 h0 = *reinterpret_cast<__half2*>(&raw.x);
        __half2 h1 = *reinterpret_cast<__half2*>(&raw.y);
        __half2 h2 = *reinterpret_cast<__half2*>(&raw.z);
        __half2 h3 = *reinterpret_cast<__half2*>(&raw.w);
        float2 f0 = __half22float2(h0);   // (B, x)
        float2 f1 = __half22float2(h1);
        float2 f2 = __half22float2(h2);
        float2 f3 = __half22float2(h3);
        acc.x = fmaf(sigmoidf_(a.x + f0.x), f0.y, acc.x);
        acc.y = fmaf(sigmoidf_(a.y + f1.x), f1.y, acc.y);
        acc.z = fmaf(sigmoidf_(a.z + f2.x), f2.y, acc.z);
        acc.w = fmaf(sigmoidf_(a.w + f3.x), f3.y, acc.w);
    }

    const float4 xv = *reinterpret_cast<const float4*>(x + (size_t)dst * FDIM + lane * 4);
    __half2 o0 = __floats2half2_rn(acc.x + xv.x, acc.y + xv.y);
    __half2 o1 = __floats2half2_rn(acc.z + xv.z, acc.w + xv.w);
    uint2 pk = make_uint2(*reinterpret_cast<uint32_t*>(&o0),
                          *reinterpret_cast<uint32_t*>(&o1));
    *reinterpret_cast<uint2*>(g_xnew16 + (size_t)dst * FDIM + lane * 4) = pk;
}

// agg2[dst] = sum_d adj[e] * x_new16[src]
__global__ __launch_bounds__(128) void spmm_kernel(
    const float* __restrict__ adj, const int* __restrict__ esrc,
    const int* __restrict__ edst)
{
    const int warp = threadIdx.x >> 5;
    const int lane = threadIdx.x & 31;
    const int node = blockIdx.x * 4 + warp;
    if (node >= NNODES) return;

    const int ebase = node * DEG;
    const int dst   = edst[ebase];

    float4 acc = make_float4(0.f, 0.f, 0.f, 0.f);

    int   srcs[DEG];
    float av[DEG];
#pragma unroll
    for (int d = 0; d < DEG; ++d) { srcs[d] = esrc[ebase + d]; av[d] = adj[ebase + d]; }

#pragma unroll
    for (int d = 0; d < DEG; ++d) {
        uint2 raw = *reinterpret_cast<const uint2*>(g_xnew16 + (size_t)srcs[d] * FDIM + lane * 4);
        __half2 h0 = *reinterpret_cast<__half2*>(&raw.x);
        __half2 h1 = *reinterpret_cast<__half2*>(&raw.y);
        float2 f0 = __half22float2(h0);
        float2 f1 = __half22float2(h1);
        acc.x = fmaf(av[d], f0.x, acc.x);
        acc.y = fmaf(av[d], f0.y, acc.y);
        acc.z = fmaf(av[d], f1.x, acc.z);
        acc.w = fmaf(av[d], f1.y, acc.w);
    }
    *reinterpret_cast<float4*>(g_agg2 + (size_t)dst * FDIM + lane * 4) = acc;
}

// ===========================================================================
extern "C" void kernel_launch(void* const* d_in, const int* in_sizes, int n_in,
                              void* d_out, int out_size)
{
    const float* x      = (const float*)d_in[0];
    const float* weight = (const float*)d_in[1];
    const float* bias   = (const float*)d_in[2];
    const float* wmask  = (const float*)d_in[3];
    const float* adj    = (const float*)d_in[4];
    const int*   esrc   = (const int*)d_in[5];
    const int*   edst   = (const int*)d_in[6];
    float*       out    = (float*)d_out;

    float *pA, *pBX, *pAgg2;
    cudaGetSymbolAddress((void**)&pA,    g_A);
    cudaGetSymbolAddress((void**)&pBX,   g_BX);
    cudaGetSymbolAddress((void**)&pAgg2, g_agg2);

    const int smem_bytes = (128 * 68 + 64 * 136) * 4;   // 69632
    cudaFuncSetAttribute(gemm_mma<0>, cudaFuncAttributeMaxDynamicSharedMemorySize, smem_bytes);
    cudaFuncSetAttribute(gemm_mma<1>, cudaFuncAttributeMaxDynamicSharedMemorySize, smem_bytes);
    cudaFuncSetAttribute(gemm_mma<2>, cudaFuncAttributeMaxDynamicSharedMemorySize, smem_bytes);

    const int gemm_blocks = (NNODES + 127) / 128;
    const int node_blocks = (NNODES + 3) / 4;

    // A = x @ Wm_top (fp32)
    gemm_mma<0><<<gemm_blocks, 256, smem_bytes>>>(x, wmask, pA, nullptr, NNODES);
    // B = x @ Wm_bot, packed with x as half2(B,x)
    gemm_mma<1><<<gemm_blocks, 256, smem_bytes>>>(x, wmask + 128 * 128, pBX, x, NNODES);
    // x_new16 = fp16(x + mask-weighted neighbor sum)
    mask_agg_kernel<<<node_blocks, 128>>>(x, esrc, edst);
    // agg2 = segment_sum(adj * x_new16[src])
    spmm_kernel<<<node_blocks, 128>>>(adj, esrc, edst);
    // out = agg2 @ weight + bias   (linearity: == segment_sum(adj*(x_new@W)) + bias)
    gemm_mma<2><<<gemm_blocks, 256, smem_bytes>>>(pAgg2, weight, out, bias, NNODES);
}

// round 5
// speedup vs baseline: 1.8238x; 1.0928x over previous
#include <cuda_runtime.h>
#include <cuda_fp16.h>
#include <cstdint>

#define NNODES 50000
#define FDIM   128
#define DEG    16

// Scratch (no allocations allowed -> __device__ globals)
__device__ float   g_A[NNODES * FDIM];         // x @ Wm_top  (fp32)
__device__ __half2 g_BX[NNODES * FDIM];        // per feature: (B_f, x_f) fp16 pair
__device__ __half  g_xnew16[NNODES * FDIM];    // fp16(x + agg)
__device__ float   g_agg2[NNODES * FDIM];      // segment_sum(adj * x_new[src])

__device__ __forceinline__ float tf32r(float v) {
    uint32_t o;
    asm("cvt.rna.tf32.f32 %0, %1;" : "=r"(o) : "f"(v));
    return __uint_as_float(o);
}
__device__ __forceinline__ uint32_t tf32u(float v) {
    uint32_t o;
    asm("cvt.rna.tf32.f32 %0, %1;" : "=r"(o) : "f"(v));
    return o;
}

__device__ __forceinline__ void mma_tf32(
    float& c0, float& c1, float& c2, float& c3,
    uint32_t a0, uint32_t a1, uint32_t a2, uint32_t a3,
    uint32_t b0, uint32_t b1)
{
    asm volatile(
        "mma.sync.aligned.m16n8k8.row.col.f32.tf32.tf32.f32 "
        "{%0,%1,%2,%3}, {%4,%5,%6,%7}, {%8,%9}, {%0,%1,%2,%3};"
        : "+f"(c0), "+f"(c1), "+f"(c2), "+f"(c3)
        : "r"(a0), "r"(a1), "r"(a2), "r"(a3), "r"(b0), "r"(b1));
}

__device__ __forceinline__ void cp16(uint32_t smem_dst, const void* gsrc, bool pred) {
    int sz = pred ? 16 : 0;   // src-size 0 -> zero-fill
    asm volatile("cp.async.cg.shared.global [%0], [%1], 16, %2;"
                 :: "r"(smem_dst), "l"(gsrc), "r"(sz));
}
#define CP_COMMIT()  asm volatile("cp.async.commit_group;" ::: "memory")
#define CP_WAIT(n)   asm volatile("cp.async.wait_group %0;" :: "n"(n) : "memory")

// Stage layout (floats): Xs[128][36] then Ws[32][136]; 8960 floats = 35840 B
#define STAGE_FLOATS (128 * 36 + 32 * 136)
#define XS_PAD 36
#define WS_PAD 136

// ===========================================================================
// C[M,128] = X[M,128] @ W[128,128]  (tf32 mma.sync, BM=128 BN=128 BK=32,
// 2-stage cp.async pipeline). 8 warps 4x2, warp tile 32x64.
// tf32 rounding (rna) applied on fragments after LDS (cp.async is raw copy).
// MODE 0: fp32 store | MODE 1: pack half2(C_f, aux_f) | MODE 2: +bias fp32
// ===========================================================================
template <int MODE>
__global__ __launch_bounds__(256, 2) void gemm_mma(
    const float* __restrict__ X, const float* __restrict__ W,
    float* __restrict__ C, const float* __restrict__ aux, int M)
{
    extern __shared__ float dyn[];

    const int tid  = threadIdx.x;
    const int lane = tid & 31;
    const int wid  = tid >> 5;
    const int wm   = wid & 3;
    const int wn   = wid >> 2;
    const int row0 = blockIdx.x * 128;
    const int lq   = lane >> 2;
    const int lr   = lane & 3;

    // per-thread fixed load slots (4 X chunks + 4 W chunks per stage)
    const int xr = tid >> 3;            // X row for chunks (tid*? see below)
    const int xc = tid & 7;             //
    const int wr = tid >> 5;            // W k-row group
    const int wc = tid & 31;

    uint32_t sbase;
    asm("{ .reg .u64 t; cvta.to.shared.u64 t, %1; cvt.u32.u64 %0, t; }"
        : "=r"(sbase) : "l"(dyn));

    // issue one stage's loads (slab = k0/32)
    auto issue_stage = [&](int slab, int stage) {
        const int k0 = slab * 32;
        const uint32_t sb = sbase + stage * STAGE_FLOATS * 4;
#pragma unroll
        for (int it = 0; it < 4; ++it) {
            int idx = tid + it * 256;
            int r = idx >> 3, c4 = idx & 7;   // 128 rows x 8 chunks
            bool ok = (row0 + r < M);
            const float* src = X + (size_t)(row0 + r) * 128 + k0 + c4 * 4;
            cp16(sb + (r * XS_PAD + c4 * 4) * 4, src, ok);
        }
        const uint32_t wb = sb + 128 * XS_PAD * 4;
#pragma unroll
        for (int it = 0; it < 4; ++it) {
            int idx = tid + it * 256;
            int kr = idx >> 5, c4 = idx & 31;  // 32 k x 32 chunks
            cp16(wb + (kr * WS_PAD + c4 * 4) * 4, W + (size_t)(k0 + kr) * 128 + c4 * 4, true);
        }
        CP_COMMIT();
    };

    float c[2][8][4];
#pragma unroll
    for (int mt = 0; mt < 2; ++mt)
#pragma unroll
        for (int nt = 0; nt < 8; ++nt)
#pragma unroll
            for (int j = 0; j < 4; ++j) c[mt][nt][j] = 0.f;

    issue_stage(0, 0);
    issue_stage(1, 1);

#pragma unroll
    for (int s = 0; s < 4; ++s) {
        if (s < 3) { CP_WAIT(1); } else { CP_WAIT(0); }
        __syncthreads();

        const float (*Xs)[XS_PAD] =
            reinterpret_cast<const float(*)[XS_PAD]>(dyn + (s & 1) * STAGE_FLOATS);
        const float (*Ws)[WS_PAD] =
            reinterpret_cast<const float(*)[WS_PAD]>(dyn + (s & 1) * STAGE_FLOATS + 128 * XS_PAD);

#pragma unroll
        for (int kk = 0; kk < 4; ++kk) {
            const int kb = kk * 8;
            uint32_t a[2][4], b[8][2];
#pragma unroll
            for (int mt = 0; mt < 2; ++mt) {
                int rb = wm * 32 + mt * 16 + lq;
                a[mt][0] = tf32u(Xs[rb    ][kb     + lr]);
                a[mt][1] = tf32u(Xs[rb + 8][kb     + lr]);
                a[mt][2] = tf32u(Xs[rb    ][kb + 4 + lr]);
                a[mt][3] = tf32u(Xs[rb + 8][kb + 4 + lr]);
            }
#pragma unroll
            for (int nt = 0; nt < 8; ++nt) {
                int col = wn * 64 + nt * 8 + lq;
                b[nt][0] = tf32u(Ws[kb     + lr][col]);
                b[nt][1] = tf32u(Ws[kb + 4 + lr][col]);
            }
#pragma unroll
            for (int mt = 0; mt < 2; ++mt)
#pragma unroll
                for (int nt = 0; nt < 8; ++nt)
                    mma_tf32(c[mt][nt][0], c[mt][nt][1], c[mt][nt][2], c[mt][nt][3],
                             a[mt][0], a[mt][1], a[mt][2], a[mt][3],
                             b[nt][0], b[nt][1]);
        }

        if (s + 2 < 4) {
            __syncthreads();           // all warps done reading stage (s&1)
            issue_stage(s + 2, s & 1);
        }
    }

    // Epilogue: c0,c1 -> (row, col..col+1), c2,c3 -> (row+8, ...)
#pragma unroll
    for (int mt = 0; mt < 2; ++mt) {
        const int r0 = row0 + wm * 32 + mt * 16 + lq;
#pragma unroll
        for (int nt = 0; nt < 8; ++nt) {
            const int col = wn * 64 + nt * 8 + 2 * lr;
            if (MODE == 0) {
                if (r0 < M)
                    *reinterpret_cast<float2*>(C + (size_t)r0 * 128 + col) =
                        make_float2(c[mt][nt][0], c[mt][nt][1]);
                if (r0 + 8 < M)
                    *reinterpret_cast<float2*>(C + (size_t)(r0 + 8) * 128 + col) =
                        make_float2(c[mt][nt][2], c[mt][nt][3]);
            } else if (MODE == 1) {
                __half2* BX = reinterpret_cast<__half2*>(C);
                if (r0 < M) {
                    float2 xv = *reinterpret_cast<const float2*>(aux + (size_t)r0 * 128 + col);
                    __half2 p0 = __floats2half2_rn(c[mt][nt][0], xv.x);
                    __half2 p1 = __floats2half2_rn(c[mt][nt][1], xv.y);
                    uint2 pk = make_uint2(*reinterpret_cast<uint32_t*>(&p0),
                                          *reinterpret_cast<uint32_t*>(&p1));
                    *reinterpret_cast<uint2*>(BX + (size_t)r0 * 128 + col) = pk;
                }
                if (r0 + 8 < M) {
                    float2 xv = *reinterpret_cast<const float2*>(aux + (size_t)(r0 + 8) * 128 + col);
                    __half2 p0 = __floats2half2_rn(c[mt][nt][2], xv.x);
                    __half2 p1 = __floats2half2_rn(c[mt][nt][3], xv.y);
                    uint2 pk = make_uint2(*reinterpret_cast<uint32_t*>(&p0),
                                          *reinterpret_cast<uint32_t*>(&p1));
                    *reinterpret_cast<uint2*>(BX + (size_t)(r0 + 8) * 128 + col) = pk;
                }
            } else {
                float2 bv = *reinterpret_cast<const float2*>(aux + col);
                if (r0 < M)
                    *reinterpret_cast<float2*>(C + (size_t)r0 * 128 + col) =
                        make_float2(c[mt][nt][0] + bv.x, c[mt][nt][1] + bv.y);
                if (r0 + 8 < M)
                    *reinterpret_cast<float2*>(C + (size_t)(r0 + 8) * 128 + col) =
                        make_float2(c[mt][nt][2] + bv.x, c[mt][nt][3] + bv.y);
            }
        }
    }
}

// ===========================================================================
// Edge kernels (LTS-gather-bound; fp16-compressed tables)
// ===========================================================================
__device__ __forceinline__ float sigmoidf_(float v) {
    return 1.0f / (1.0f + __expf(-v));
}

// x_new16[dst] = fp16( x[dst] + sum_d sigmoid(A[dst] + B[src]) * x[src] )
__global__ __launch_bounds__(128) void mask_agg_kernel(
    const float* __restrict__ x, const int* __restrict__ esrc,
    const int* __restrict__ edst)
{
    const int warp = threadIdx.x >> 5;
    const int lane = threadIdx.x & 31;
    const int node = blockIdx.x * 4 + warp;
    if (node >= NNODES) return;

    const int ebase = node * DEG;
    const int dst   = edst[ebase];

    const float4 a = *reinterpret_cast<const float4*>(g_A + (size_t)dst * FDIM + lane * 4);
    float4 acc = make_float4(0.f, 0.f, 0.f, 0.f);

    int srcs[DEG];
#pragma unroll
    for (int d = 0; d < DEG; ++d) srcs[d] = esrc[ebase + d];

#pragma unroll
    for (int d = 0; d < DEG; ++d) {
        uint4 raw = *reinterpret_cast<const uint4*>(g_BX + (size_t)srcs[d] * FDIM + lane * 4);
        float2 f0 = __half22float2(*reinterpret_cast<__half2*>(&raw.x));
        float2 f1 = __half22float2(*reinterpret_cast<__half2*>(&raw.y));
        float2 f2 = __half22float2(*reinterpret_cast<__half2*>(&raw.z));
        float2 f3 = __half22float2(*reinterpret_cast<__half2*>(&raw.w));
        acc.x = fmaf(sigmoidf_(a.x + f0.x), f0.y, acc.x);
        acc.y = fmaf(sigmoidf_(a.y + f1.x), f1.y, acc.y);
        acc.z = fmaf(sigmoidf_(a.z + f2.x), f2.y, acc.z);
        acc.w = fmaf(sigmoidf_(a.w + f3.x), f3.y, acc.w);
    }

    const float4 xv = *reinterpret_cast<const float4*>(x + (size_t)dst * FDIM + lane * 4);
    __half2 o0 = __floats2half2_rn(acc.x + xv.x, acc.y + xv.y);
    __half2 o1 = __floats2half2_rn(acc.z + xv.z, acc.w + xv.w);
    uint2 pk = make_uint2(*reinterpret_cast<uint32_t*>(&o0),
                          *reinterpret_cast<uint32_t*>(&o1));
    *reinterpret_cast<uint2*>(g_xnew16 + (size_t)dst * FDIM + lane * 4) = pk;
}

// agg2[dst] = sum_d adj[e] * x_new16[src]
__global__ __launch_bounds__(128) void spmm_kernel(
    const float* __restrict__ adj, const int* __restrict__ esrc,
    const int* __restrict__ edst)
{
    const int warp = threadIdx.x >> 5;
    const int lane = threadIdx.x & 31;
    const int node = blockIdx.x * 4 + warp;
    if (node >= NNODES) return;

    const int ebase = node * DEG;
    const int dst   = edst[ebase];

    float4 acc = make_float4(0.f, 0.f, 0.f, 0.f);

    int   srcs[DEG];
    float av[DEG];
#pragma unroll
    for (int d = 0; d < DEG; ++d) { srcs[d] = esrc[ebase + d]; av[d] = adj[ebase + d]; }

#pragma unroll
    for (int d = 0; d < DEG; ++d) {
        uint2 raw = *reinterpret_cast<const uint2*>(g_xnew16 + (size_t)srcs[d] * FDIM + lane * 4);
        float2 f0 = __half22float2(*reinterpret_cast<__half2*>(&raw.x));
        float2 f1 = __half22float2(*reinterpret_cast<__half2*>(&raw.y));
        acc.x = fmaf(av[d], f0.x, acc.x);
        acc.y = fmaf(av[d], f0.y, acc.y);
        acc.z = fmaf(av[d], f1.x, acc.z);
        acc.w = fmaf(av[d], f1.y, acc.w);
    }
    *reinterpret_cast<float4*>(g_agg2 + (size_t)dst * FDIM + lane * 4) = acc;
}

// ===========================================================================
extern "C" void kernel_launch(void* const* d_in, const int* in_sizes, int n_in,
                              void* d_out, int out_size)
{
    const float* x      = (const float*)d_in[0];
    const float* weight = (const float*)d_in[1];
    const float* bias   = (const float*)d_in[2];
    const float* wmask  = (const float*)d_in[3];
    const float* adj    = (const float*)d_in[4];
    const int*   esrc   = (const int*)d_in[5];
    const int*   edst   = (const int*)d_in[6];
    float*       out    = (float*)d_out;

    float *pA, *pBX, *pAgg2;
    cudaGetSymbolAddress((void**)&pA,    g_A);
    cudaGetSymbolAddress((void**)&pBX,   g_BX);
    cudaGetSymbolAddress((void**)&pAgg2, g_agg2);

    const int smem_bytes = 2 * STAGE_FLOATS * 4;   // 71680
    cudaFuncSetAttribute(gemm_mma<0>, cudaFuncAttributeMaxDynamicSharedMemorySize, smem_bytes);
    cudaFuncSetAttribute(gemm_mma<1>, cudaFuncAttributeMaxDynamicSharedMemorySize, smem_bytes);
    cudaFuncSetAttribute(gemm_mma<2>, cudaFuncAttributeMaxDynamicSharedMemorySize, smem_bytes);

    const int gemm_blocks = (NNODES + 127) / 128;
    const int node_blocks = (NNODES + 3) / 4;

    // A = x @ Wm_top (fp32)
    gemm_mma<0><<<gemm_blocks, 256, smem_bytes>>>(x, wmask, pA, nullptr, NNODES);
    // B = x @ Wm_bot, packed with x as half2(B,x)
    gemm_mma<1><<<gemm_blocks, 256, smem_bytes>>>(x, wmask + 128 * 128, pBX, x, NNODES);
    // x_new16 = fp16(x + mask-weighted neighbor sum)
    mask_agg_kernel<<<node_blocks, 128>>>(x, esrc, edst);
    // agg2 = segment_sum(adj * x_new16[src])
    spmm_kernel<<<node_blocks, 128>>>(adj, esrc, edst);
    // out = agg2 @ weight + bias   (linearity: == segment_sum(adj*(x_new@W)) + bias)
    gemm_mma<2><<<gemm_blocks, 256, smem_bytes>>>(pAgg2, weight, out, bias, NNODES);
}